// round 13
// baseline (speedup 1.0000x reference)
#include <cuda_runtime.h>
#include <cuda_fp16.h>
#include <mma.h>
#include <math.h>

using namespace nvcuda;

#define NMAX 50000
#define EMAX 1600000
#define IN_DIM 128
#define F1 128          // HEADS*HID
#define HEADS 4
#define OUT_D 32

// ---- scratch (static __device__, no allocation) ----
__device__ __half g_W1h[IN_DIM * F1];        // fp16 copy of W1
__device__ __half g_z1h[NMAX * F1];          // fp16 layer1 linear output (gather payload)
__device__ float g_el1[NMAX * HEADS];
__device__ float g_er1[NMAX * HEADS];
__device__ __half g_z2h[NMAX * OUT_D];       // fp16 layer2 linear output
__device__ float g_el2[NMAX];
__device__ float g_er2[NMAX];
// CSR
__device__ int g_cnt[NMAX];
__device__ int g_rowstart[NMAX];
__device__ int g_rank[EMAX];
__device__ int g_csrsrc[EMAX];
__device__ int g_total;

__device__ __forceinline__ float lrelu(float v) { return v > 0.f ? v : 0.2f * v; }
__device__ __forceinline__ float elu1(float v) { return v > 0.f ? v : expm1f(v); }

// ================= CSR build =================
// hist: 16 edges/thread, records each edge's rank within its dst bucket
__global__ void k_hist(const int* __restrict__ dst, int E) {
    int e = (blockIdx.x * blockDim.x + threadIdx.x) * 16;
    if (e + 15 < E) {
#pragma unroll
        for (int g = 0; g < 4; g++) {
            int4 d4 = *(const int4*)&dst[e + 4 * g];
            int4 r4;
            r4.x = atomicAdd(&g_cnt[d4.x], 1);
            r4.y = atomicAdd(&g_cnt[d4.y], 1);
            r4.z = atomicAdd(&g_cnt[d4.z], 1);
            r4.w = atomicAdd(&g_cnt[d4.w], 1);
            *(int4*)&g_rank[e + 4 * g] = r4;
        }
    } else {
        for (int r = 0; r < 16; r++)
            if (e + r < E) g_rank[e + r] = atomicAdd(&g_cnt[dst[e + r]], 1);
    }
}

// warp-aggregated offsets: shuffle-scan + 1 atomic per warp
__global__ void k_offsets(int n) {
    int i = blockIdx.x * blockDim.x + threadIdx.x;
    int lane = threadIdx.x & 31;
    int c = (i < n) ? g_cnt[i] : 0;
    int inc = c;
#pragma unroll
    for (int off = 1; off < 32; off <<= 1) {
        int v = __shfl_up_sync(0xffffffffu, inc, off);
        if (lane >= off) inc += v;
    }
    int total = __shfl_sync(0xffffffffu, inc, 31);
    int base = 0;
    if (lane == 31) base = atomicAdd(&g_total, total);
    base = __shfl_sync(0xffffffffu, base, 31);
    if (i < n) g_rowstart[i] = base + inc - c;
}

// atomic-free scatter: pos = rowstart[dst] + rank; 16 edges/thread
__global__ void k_scatter(const int* __restrict__ src, const int* __restrict__ dst, int E) {
    int e = (blockIdx.x * blockDim.x + threadIdx.x) * 16;
    if (e + 15 < E) {
#pragma unroll
        for (int g = 0; g < 4; g++) {
            int4 d4 = *(const int4*)&dst[e + 4 * g];
            int4 s4 = *(const int4*)&src[e + 4 * g];
            int4 r4 = *(const int4*)&g_rank[e + 4 * g];
            g_csrsrc[g_rowstart[d4.x] + r4.x] = s4.x;
            g_csrsrc[g_rowstart[d4.y] + r4.y] = s4.y;
            g_csrsrc[g_rowstart[d4.z] + r4.z] = s4.z;
            g_csrsrc[g_rowstart[d4.w] + r4.w] = s4.w;
        }
    } else {
        for (int r = 0; r < 16; r++) {
            if (e + r < E)
                g_csrsrc[g_rowstart[dst[e + r]] + g_rank[e + r]] = src[e + r];
        }
    }
}

// ================= layer 1 =================
__global__ void k_w1h(const float* __restrict__ W1) {
    int i = blockIdx.x * blockDim.x + threadIdx.x;
    if (i < IN_DIM * F1) g_W1h[i] = __float2half_rn(W1[i]);
}

// GEMM1 via wmma (HMMA): 32 rows/block, 128 threads (4 warps).
__global__ void __launch_bounds__(128) k_gemm1(
    const float* __restrict__ h, const float* __restrict__ al,
    const float* __restrict__ ar, int n) {
    __shared__ __align__(16) __half As[32][136];
    __shared__ __align__(16) float Cs[32][128];
    int n0 = blockIdx.x * 32;
    int t = threadIdx.x;

    for (int idx = t; idx < 32 * IN_DIM; idx += 128) {
        int r = idx >> 7, c = idx & 127;
        int gr = n0 + r;
        float v = (gr < n) ? h[(size_t)gr * IN_DIM + c] : 0.f;
        As[r][c] = __float2half_rn(v);
    }
    __syncthreads();

    int w = t >> 5;
    int mt = w & 1;
    int c0 = (w >> 1) * 4;

    wmma::fragment<wmma::accumulator, 16, 16, 16, float> acc[4];
#pragma unroll
    for (int q = 0; q < 4; q++) wmma::fill_fragment(acc[q], 0.f);

#pragma unroll
    for (int k = 0; k < 8; k++) {
        wmma::fragment<wmma::matrix_a, 16, 16, 16, __half, wmma::row_major> a;
        wmma::load_matrix_sync(a, &As[mt * 16][k * 16], 136);
#pragma unroll
        for (int q = 0; q < 4; q++) {
            wmma::fragment<wmma::matrix_b, 16, 16, 16, __half, wmma::row_major> b;
            wmma::load_matrix_sync(b, &g_W1h[(k * 16) * F1 + (c0 + q) * 16], F1);
            wmma::mma_sync(acc[q], a, b, acc[q]);
        }
    }
#pragma unroll
    for (int q = 0; q < 4; q++)
        wmma::store_matrix_sync(&Cs[mt * 16][(c0 + q) * 16], acc[q], 128,
                                wmma::mem_row_major);
    __syncthreads();

    int lane = t & 31;
    int hh = t >> 5;
    float av = al[t], rv = ar[t];
    for (int r = 0; r < 32; r++) {
        int row = n0 + r;
        float z = Cs[r][t];
        if (row < n) g_z1h[(size_t)row * F1 + t] = __float2half_rn(z);
        float el = z * av, er = z * rv;
#pragma unroll
        for (int off = 16; off; off >>= 1) {
            el += __shfl_xor_sync(0xffffffffu, el, off);
            er += __shfl_xor_sync(0xffffffffu, er, off);
        }
        if (lane == 0 && row < n) {
            g_el1[row * HEADS + hh] = el;
            g_er1[row * HEADS + hh] = er;
        }
    }
}

// FUSED aggregation layer1 + GEMM2 + el2/er2.
// One warp per node. Phase 1: CSR gather + softmax-weighted sum (2 edges in
// flight via half-warps). Phase 2: x-row -> smem, each lane computes one of
// the 32 layer-2 columns against smem-staged W2, then butterfly el2/er2.
__global__ void __launch_bounds__(256) k_aggr1(
    const float* __restrict__ b1, const float* __restrict__ W2,
    const float* __restrict__ al2, const float* __restrict__ ar2, int n) {
    __shared__ float W2s[IN_DIM][OUT_D];     // 16 KB
    __shared__ float xrow[8][IN_DIM];        // 4 KB (per-warp x buffer)
    int t = threadIdx.x;
    for (int idx = t; idx < IN_DIM * OUT_D; idx += 256)
        W2s[idx >> 5][idx & 31] = W2[idx];
    __syncthreads();

    int wp = t >> 5;
    int d = blockIdx.x * 8 + wp;
    bool active = d < n;
    int lane = t & 31;
    int half = lane >> 4;
    int l = lane & 15;            // channel group: channels 8l..8l+7
    int hh = l >> 2;

    float er = active ? g_er1[d * HEADS + hh] : 0.f;
    int beg = 0, end = 0;
    if (active) { beg = g_rowstart[d]; end = beg + g_cnt[d]; }

    float acc[8] = {0.f, 0.f, 0.f, 0.f, 0.f, 0.f, 0.f, 0.f};
    float sacc = 0.f;
    int i = beg + half;
    for (; i + 6 < end; i += 8) {
        int s[4];
#pragma unroll
        for (int u = 0; u < 4; u++) s[u] = __ldg(&g_csrsrc[i + 2 * u]);
        float ev[4];
        uint4 uz[4];
#pragma unroll
        for (int u = 0; u < 4; u++) {
            ev[u] = __ldg(&g_el1[s[u] * HEADS + hh]);
            uz[u] = *(const uint4*)&g_z1h[(size_t)s[u] * F1 + l * 8];
        }
#pragma unroll
        for (int u = 0; u < 4; u++) {
            float x = __expf(lrelu(ev[u] + er));
            sacc += x;
            float2 p0 = __half22float2(*(__half2*)&uz[u].x);
            float2 p1 = __half22float2(*(__half2*)&uz[u].y);
            float2 p2 = __half22float2(*(__half2*)&uz[u].z);
            float2 p3 = __half22float2(*(__half2*)&uz[u].w);
            acc[0] += x * p0.x; acc[1] += x * p0.y;
            acc[2] += x * p1.x; acc[3] += x * p1.y;
            acc[4] += x * p2.x; acc[5] += x * p2.y;
            acc[6] += x * p3.x; acc[7] += x * p3.y;
        }
    }
    for (; i < end; i += 2) {
        int s0 = __ldg(&g_csrsrc[i]);
        float e0 = __ldg(&g_el1[s0 * HEADS + hh]);
        uint4 uz = *(const uint4*)&g_z1h[(size_t)s0 * F1 + l * 8];
        float x = __expf(lrelu(e0 + er));
        sacc += x;
        float2 p0 = __half22float2(*(__half2*)&uz.x);
        float2 p1 = __half22float2(*(__half2*)&uz.y);
        float2 p2 = __half22float2(*(__half2*)&uz.z);
        float2 p3 = __half22float2(*(__half2*)&uz.w);
        acc[0] += x * p0.x; acc[1] += x * p0.y;
        acc[2] += x * p1.x; acc[3] += x * p1.y;
        acc[4] += x * p2.x; acc[5] += x * p2.y;
        acc[6] += x * p3.x; acc[7] += x * p3.y;
    }
    // merge halves
    sacc += __shfl_xor_sync(0xffffffffu, sacc, 16);
#pragma unroll
    for (int k = 0; k < 8; k++)
        acc[k] += __shfl_xor_sync(0xffffffffu, acc[k], 16);

    if (active && half == 0) {
        float inv = (sacc > 0.f) ? __fdividef(1.f, sacc) : 0.f;
        float4 bA = *(const float4*)&b1[l * 8];
        float4 bB = *(const float4*)&b1[l * 8 + 4];
        float4 o1, o2;
        o1.x = elu1(acc[0] * inv + bA.x);
        o1.y = elu1(acc[1] * inv + bA.y);
        o1.z = elu1(acc[2] * inv + bA.z);
        o1.w = elu1(acc[3] * inv + bA.w);
        o2.x = elu1(acc[4] * inv + bB.x);
        o2.y = elu1(acc[5] * inv + bB.y);
        o2.z = elu1(acc[6] * inv + bB.z);
        o2.w = elu1(acc[7] * inv + bB.w);
        *(float4*)&xrow[wp][l * 8] = o1;
        *(float4*)&xrow[wp][l * 8 + 4] = o2;
    }
    __syncwarp();

    // phase 2: layer-2 linear for this node; lane = output column
    if (active) {
        float accg = 0.f;
#pragma unroll
        for (int k = 0; k < IN_DIM; k += 4) {
            float4 xv = *(const float4*)&xrow[wp][k];
            accg += xv.x * W2s[k][lane] + xv.y * W2s[k + 1][lane]
                  + xv.z * W2s[k + 2][lane] + xv.w * W2s[k + 3][lane];
        }
        g_z2h[(size_t)d * OUT_D + lane] = __float2half_rn(accg);
        float el = accg * al2[lane];
        float e2 = accg * ar2[lane];
#pragma unroll
        for (int off = 16; off; off >>= 1) {
            el += __shfl_xor_sync(0xffffffffu, el, off);
            e2 += __shfl_xor_sync(0xffffffffu, e2, off);
        }
        if (lane == 0) { g_el2[d] = el; g_er2[d] = e2; }
    }
}

// aggregation layer2: one warp per node; 4 edges in flight (quarter-warps)
__global__ void k_aggr2(float* __restrict__ out, const float* __restrict__ b2, int n) {
    int d = blockIdx.x * (blockDim.x >> 5) + (threadIdx.x >> 5);
    if (d >= n) return;
    int lane = threadIdx.x & 31;
    int quarter = lane >> 3;
    int q = lane & 7;
    float er = g_er2[d];
    int beg = g_rowstart[d];
    int end = beg + g_cnt[d];
    float acc[4] = {0.f, 0.f, 0.f, 0.f};
    float sacc = 0.f;
    int i = beg + quarter;
    for (; i + 4 < end; i += 8) {
        int s0 = __ldg(&g_csrsrc[i]);
        int s1 = __ldg(&g_csrsrc[i + 4]);
        float e0 = __ldg(&g_el2[s0]);
        float e1 = __ldg(&g_el2[s1]);
        uint2 u0 = *(const uint2*)&g_z2h[(size_t)s0 * OUT_D + q * 4];
        uint2 u1 = *(const uint2*)&g_z2h[(size_t)s1 * OUT_D + q * 4];
        float x0 = __expf(lrelu(e0 + er));
        float x1 = __expf(lrelu(e1 + er));
        sacc += x0 + x1;
        float2 a0 = __half22float2(*(__half2*)&u0.x);
        float2 b0 = __half22float2(*(__half2*)&u0.y);
        float2 a1 = __half22float2(*(__half2*)&u1.x);
        float2 b1v = __half22float2(*(__half2*)&u1.y);
        acc[0] += x0 * a0.x + x1 * a1.x;
        acc[1] += x0 * a0.y + x1 * a1.y;
        acc[2] += x0 * b0.x + x1 * b1v.x;
        acc[3] += x0 * b0.y + x1 * b1v.y;
    }
    for (; i < end; i += 4) {
        int s0 = __ldg(&g_csrsrc[i]);
        float e0 = __ldg(&g_el2[s0]);
        uint2 u0 = *(const uint2*)&g_z2h[(size_t)s0 * OUT_D + q * 4];
        float x0 = __expf(lrelu(e0 + er));
        sacc += x0;
        float2 a0 = __half22float2(*(__half2*)&u0.x);
        float2 b0 = __half22float2(*(__half2*)&u0.y);
        acc[0] += x0 * a0.x;
        acc[1] += x0 * a0.y;
        acc[2] += x0 * b0.x;
        acc[3] += x0 * b0.y;
    }
#pragma unroll
    for (int off = 8; off <= 16; off <<= 1) {
        sacc += __shfl_xor_sync(0xffffffffu, sacc, off);
#pragma unroll
        for (int k = 0; k < 4; k++)
            acc[k] += __shfl_xor_sync(0xffffffffu, acc[k], off);
    }
    if (lane < 8) {
        float inv = (sacc > 0.f) ? __fdividef(1.f, sacc) : 0.f;
        float4 bb = *(const float4*)&b2[q * 4];
        float4 o;
        o.x = acc[0] * inv + bb.x;
        o.y = acc[1] * inv + bb.y;
        o.z = acc[2] * inv + bb.z;
        o.w = acc[3] * inv + bb.w;
        *(float4*)&out[(size_t)d * OUT_D + q * 4] = o;
    }
}

extern "C" void kernel_launch(void* const* d_in, const int* in_sizes, int n_in,
                              void* d_out, int out_size) {
    const float* h   = (const float*)d_in[0];
    const int*   src = (const int*)d_in[1];
    const int*   dst = (const int*)d_in[2];
    const float* W1  = (const float*)d_in[3];
    const float* al1 = (const float*)d_in[4];
    const float* ar1 = (const float*)d_in[5];
    const float* b1  = (const float*)d_in[6];
    const float* W2  = (const float*)d_in[7];
    const float* al2 = (const float*)d_in[8];
    const float* ar2 = (const float*)d_in[9];
    const float* b2  = (const float*)d_in[10];
    float* out = (float*)d_out;

    int n = in_sizes[0] / IN_DIM;
    int E = in_sizes[1];
    if (n > NMAX) n = NMAX;
    if (E > EMAX) E = EMAX;

    static cudaStream_t s2 = nullptr, s3 = nullptr;
    static cudaEvent_t evF = nullptr, evCSR = nullptr, evG1 = nullptr;
    static void* p_cnt = nullptr;
    static void* p_total = nullptr;
    if (s2 == nullptr) {
        cudaStreamCreateWithFlags(&s2, cudaStreamNonBlocking);
        cudaStreamCreateWithFlags(&s3, cudaStreamNonBlocking);
        cudaEventCreateWithFlags(&evF, cudaEventDisableTiming);
        cudaEventCreateWithFlags(&evCSR, cudaEventDisableTiming);
        cudaEventCreateWithFlags(&evG1, cudaEventDisableTiming);
        cudaGetSymbolAddress(&p_cnt, g_cnt);
        cudaGetSymbolAddress(&p_total, g_total);
    }

    // fork: both branches on non-legacy streams
    cudaEventRecord(evF, 0);
    cudaStreamWaitEvent(s2, evF, 0);
    cudaStreamWaitEvent(s3, evF, 0);

    // branch A (s2): CSR build
    cudaMemsetAsync(p_cnt, 0, (size_t)n * sizeof(int), s2);
    cudaMemsetAsync(p_total, 0, sizeof(int), s2);
    k_hist<<<(E / 16 + 255) / 256, 256, 0, s2>>>(dst, E);
    k_offsets<<<(n + 255) / 256, 256, 0, s2>>>(n);
    k_scatter<<<(E / 16 + 255) / 256, 256, 0, s2>>>(src, dst, E);
    cudaEventRecord(evCSR, s2);

    // branch B (s3): W1->fp16 then tensor-core GEMM1
    k_w1h<<<(IN_DIM * F1 + 255) / 256, 256, 0, s3>>>(W1);
    k_gemm1<<<(n + 31) / 32, 128, 0, s3>>>(h, al1, ar1, n);
    cudaEventRecord(evG1, s3);

    // join
    cudaStreamWaitEvent(0, evCSR, 0);
    cudaStreamWaitEvent(0, evG1, 0);

    k_aggr1<<<(n + 7) / 8, 256>>>(b1, W2, al2, ar2, n);
    k_aggr2<<<(n + 7) / 8, 256>>>(out, b2, n);
}

// round 14
// speedup vs baseline: 1.0012x; 1.0012x over previous
#include <cuda_runtime.h>
#include <cuda_fp16.h>
#include <mma.h>
#include <math.h>

using namespace nvcuda;

#define NMAX 50000
#define EMAX 1600000
#define IN_DIM 128
#define F1 128          // HEADS*HID
#define HEADS 4
#define OUT_D 32

// ---- scratch (static __device__, no allocation) ----
__device__ __half g_W1h[IN_DIM * F1];        // fp16 copy of W1
__device__ __half g_z1h[NMAX * F1];          // fp16 layer1 linear output (gather payload)
__device__ float g_el1[NMAX * HEADS];
__device__ float g_er1[NMAX * HEADS];
__device__ float g_x1[NMAX * F1];            // layer1 output (normalized + bias + elu)
__device__ __half g_z2h[NMAX * OUT_D];       // fp16 layer2 linear output
__device__ float g_el2[NMAX];
__device__ float g_er2[NMAX];
// CSR
__device__ int g_cnt[NMAX];
__device__ int g_rowstart[NMAX];
__device__ int g_rank[EMAX];
__device__ int g_csrsrc[EMAX];
__device__ int g_total;

__device__ __forceinline__ float lrelu(float v) { return v > 0.f ? v : 0.2f * v; }
__device__ __forceinline__ float elu1(float v) { return v > 0.f ? v : expm1f(v); }

// ---- packed fp32x2 FMA ----
__device__ __forceinline__ unsigned long long pack2(float a, float b) {
    unsigned long long r;
    asm("mov.b64 %0, {%1, %2};" : "=l"(r) : "f"(a), "f"(b));
    return r;
}
__device__ __forceinline__ void ffma2(unsigned long long& acc, unsigned long long a,
                                      unsigned long long b) {
    asm("fma.rn.f32x2 %0, %1, %2, %0;" : "+l"(acc) : "l"(a), "l"(b));
}
__device__ __forceinline__ float hsum2(unsigned long long v) {
    float lo, hi;
    asm("mov.b64 {%0, %1}, %2;" : "=f"(lo), "=f"(hi) : "l"(v));
    return lo + hi;
}

// ================= CSR build =================
// hist: 16 edges/thread, records each edge's rank within its dst bucket
__global__ void k_hist(const int* __restrict__ dst, int E) {
    int e = (blockIdx.x * blockDim.x + threadIdx.x) * 16;
    if (e + 15 < E) {
#pragma unroll
        for (int g = 0; g < 4; g++) {
            int4 d4 = *(const int4*)&dst[e + 4 * g];
            int4 r4;
            r4.x = atomicAdd(&g_cnt[d4.x], 1);
            r4.y = atomicAdd(&g_cnt[d4.y], 1);
            r4.z = atomicAdd(&g_cnt[d4.z], 1);
            r4.w = atomicAdd(&g_cnt[d4.w], 1);
            *(int4*)&g_rank[e + 4 * g] = r4;
        }
    } else {
        for (int r = 0; r < 16; r++)
            if (e + r < E) g_rank[e + r] = atomicAdd(&g_cnt[dst[e + r]], 1);
    }
}

// warp-aggregated offsets: shuffle-scan + 1 atomic per warp
__global__ void k_offsets(int n) {
    int i = blockIdx.x * blockDim.x + threadIdx.x;
    int lane = threadIdx.x & 31;
    int c = (i < n) ? g_cnt[i] : 0;
    int inc = c;
#pragma unroll
    for (int off = 1; off < 32; off <<= 1) {
        int v = __shfl_up_sync(0xffffffffu, inc, off);
        if (lane >= off) inc += v;
    }
    int total = __shfl_sync(0xffffffffu, inc, 31);
    int base = 0;
    if (lane == 31) base = atomicAdd(&g_total, total);
    base = __shfl_sync(0xffffffffu, base, 31);
    if (i < n) g_rowstart[i] = base + inc - c;
}

// atomic-free scatter: pos = rowstart[dst] + rank; 16 edges/thread
__global__ void k_scatter(const int* __restrict__ src, const int* __restrict__ dst, int E) {
    int e = (blockIdx.x * blockDim.x + threadIdx.x) * 16;
    if (e + 15 < E) {
#pragma unroll
        for (int g = 0; g < 4; g++) {
            int4 d4 = *(const int4*)&dst[e + 4 * g];
            int4 s4 = *(const int4*)&src[e + 4 * g];
            int4 r4 = *(const int4*)&g_rank[e + 4 * g];
            g_csrsrc[g_rowstart[d4.x] + r4.x] = s4.x;
            g_csrsrc[g_rowstart[d4.y] + r4.y] = s4.y;
            g_csrsrc[g_rowstart[d4.z] + r4.z] = s4.z;
            g_csrsrc[g_rowstart[d4.w] + r4.w] = s4.w;
        }
    } else {
        for (int r = 0; r < 16; r++) {
            if (e + r < E)
                g_csrsrc[g_rowstart[dst[e + r]] + g_rank[e + r]] = src[e + r];
        }
    }
}

// ================= layer 1 =================
__global__ void k_w1h(const float* __restrict__ W1) {
    int i = blockIdx.x * blockDim.x + threadIdx.x;
    if (i < IN_DIM * F1) g_W1h[i] = __float2half_rn(W1[i]);
}

// GEMM1 via wmma (HMMA): 32 rows/block, 128 threads (4 warps).
__global__ void __launch_bounds__(128) k_gemm1(
    const float* __restrict__ h, const float* __restrict__ al,
    const float* __restrict__ ar, int n) {
    __shared__ __align__(16) __half As[32][136];
    __shared__ __align__(16) float Cs[32][128];
    int n0 = blockIdx.x * 32;
    int t = threadIdx.x;

    for (int idx = t; idx < 32 * IN_DIM; idx += 128) {
        int r = idx >> 7, c = idx & 127;
        int gr = n0 + r;
        float v = (gr < n) ? h[(size_t)gr * IN_DIM + c] : 0.f;
        As[r][c] = __float2half_rn(v);
    }
    __syncthreads();

    int w = t >> 5;
    int mt = w & 1;
    int c0 = (w >> 1) * 4;

    wmma::fragment<wmma::accumulator, 16, 16, 16, float> acc[4];
#pragma unroll
    for (int q = 0; q < 4; q++) wmma::fill_fragment(acc[q], 0.f);

#pragma unroll
    for (int k = 0; k < 8; k++) {
        wmma::fragment<wmma::matrix_a, 16, 16, 16, __half, wmma::row_major> a;
        wmma::load_matrix_sync(a, &As[mt * 16][k * 16], 136);
#pragma unroll
        for (int q = 0; q < 4; q++) {
            wmma::fragment<wmma::matrix_b, 16, 16, 16, __half, wmma::row_major> b;
            wmma::load_matrix_sync(b, &g_W1h[(k * 16) * F1 + (c0 + q) * 16], F1);
            wmma::mma_sync(acc[q], a, b, acc[q]);
        }
    }
#pragma unroll
    for (int q = 0; q < 4; q++)
        wmma::store_matrix_sync(&Cs[mt * 16][(c0 + q) * 16], acc[q], 128,
                                wmma::mem_row_major);
    __syncthreads();

    int lane = t & 31;
    int hh = t >> 5;
    float av = al[t], rv = ar[t];
    for (int r = 0; r < 32; r++) {
        int row = n0 + r;
        float z = Cs[r][t];
        if (row < n) g_z1h[(size_t)row * F1 + t] = __float2half_rn(z);
        float el = z * av, er = z * rv;
#pragma unroll
        for (int off = 16; off; off >>= 1) {
            el += __shfl_xor_sync(0xffffffffu, el, off);
            er += __shfl_xor_sync(0xffffffffu, er, off);
        }
        if (lane == 0 && row < n) {
            g_el1[row * HEADS + hh] = el;
            g_er1[row * HEADS + hh] = er;
        }
    }
}

// aggregation layer1: one warp per node; 2 edges in flight (half-warps),
// 8-edge unroll per half (MLP ~16), each lane loads 8 fp16 channels (uint4).
__global__ void k_aggr1(const float* __restrict__ b1, int n) {
    int d = blockIdx.x * (blockDim.x >> 5) + (threadIdx.x >> 5);
    if (d >= n) return;
    int lane = threadIdx.x & 31;
    int half = lane >> 4;
    int l = lane & 15;            // channel group: channels 8l..8l+7
    int hh = l >> 2;
    float er = g_er1[d * HEADS + hh];
    int beg = g_rowstart[d];
    int end = beg + g_cnt[d];
    float acc[8] = {0.f, 0.f, 0.f, 0.f, 0.f, 0.f, 0.f, 0.f};
    float sacc = 0.f;
    int i = beg + half;
    // main: 8 edges per half per iter (16 edges/warp/iter)
    for (; i + 14 < end; i += 16) {
        int s[8];
#pragma unroll
        for (int u = 0; u < 8; u++) s[u] = __ldg(&g_csrsrc[i + 2 * u]);
        float ev[8];
        uint4 uz[8];
#pragma unroll
        for (int u = 0; u < 8; u++) {
            ev[u] = __ldg(&g_el1[s[u] * HEADS + hh]);
            uz[u] = *(const uint4*)&g_z1h[(size_t)s[u] * F1 + l * 8];
        }
#pragma unroll
        for (int u = 0; u < 8; u++) {
            float x = __expf(lrelu(ev[u] + er));
            sacc += x;
            float2 p0 = __half22float2(*(__half2*)&uz[u].x);
            float2 p1 = __half22float2(*(__half2*)&uz[u].y);
            float2 p2 = __half22float2(*(__half2*)&uz[u].z);
            float2 p3 = __half22float2(*(__half2*)&uz[u].w);
            acc[0] += x * p0.x; acc[1] += x * p0.y;
            acc[2] += x * p1.x; acc[3] += x * p1.y;
            acc[4] += x * p2.x; acc[5] += x * p2.y;
            acc[6] += x * p3.x; acc[7] += x * p3.y;
        }
    }
    for (; i < end; i += 2) {
        int s0 = __ldg(&g_csrsrc[i]);
        float e0 = __ldg(&g_el1[s0 * HEADS + hh]);
        uint4 uz = *(const uint4*)&g_z1h[(size_t)s0 * F1 + l * 8];
        float x = __expf(lrelu(e0 + er));
        sacc += x;
        float2 p0 = __half22float2(*(__half2*)&uz.x);
        float2 p1 = __half22float2(*(__half2*)&uz.y);
        float2 p2 = __half22float2(*(__half2*)&uz.z);
        float2 p3 = __half22float2(*(__half2*)&uz.w);
        acc[0] += x * p0.x; acc[1] += x * p0.y;
        acc[2] += x * p1.x; acc[3] += x * p1.y;
        acc[4] += x * p2.x; acc[5] += x * p2.y;
        acc[6] += x * p3.x; acc[7] += x * p3.y;
    }
    // merge halves
    sacc += __shfl_xor_sync(0xffffffffu, sacc, 16);
#pragma unroll
    for (int k = 0; k < 8; k++)
        acc[k] += __shfl_xor_sync(0xffffffffu, acc[k], 16);
    if (half == 0) {
        float inv = (sacc > 0.f) ? __fdividef(1.f, sacc) : 0.f;
        float4 bA = *(const float4*)&b1[l * 8];
        float4 bB = *(const float4*)&b1[l * 8 + 4];
        float4 o1, o2;
        o1.x = elu1(acc[0] * inv + bA.x);
        o1.y = elu1(acc[1] * inv + bA.y);
        o1.z = elu1(acc[2] * inv + bA.z);
        o1.w = elu1(acc[3] * inv + bA.w);
        o2.x = elu1(acc[4] * inv + bB.x);
        o2.y = elu1(acc[5] * inv + bB.y);
        o2.z = elu1(acc[6] * inv + bB.z);
        o2.w = elu1(acc[7] * inv + bB.w);
        *(float4*)&g_x1[(size_t)d * F1 + l * 8] = o1;
        *(float4*)&g_x1[(size_t)d * F1 + l * 8 + 4] = o2;
    }
}

// ================= layer 2 =================
__global__ void k_gemm2(const float* __restrict__ W2, const float* __restrict__ al,
                        const float* __restrict__ ar, int n) {
    __shared__ float xs[16][IN_DIM];
    int n0 = blockIdx.x * 16;
    int t = threadIdx.x;
    int lane = t & 31;
#pragma unroll
    for (int j = 0; j < 16; j++) {
        int row = n0 + j;
        xs[j][t] = (row < n) ? g_x1[(size_t)row * F1 + t] : 0.f;
    }
    __syncthreads();
    int c = t & 31;
    int jg = t >> 5;
    unsigned long long acc2[4] = {0ull, 0ull, 0ull, 0ull};
#pragma unroll 2
    for (int k = 0; k < IN_DIM; k += 4) {
        float w0 = __ldg(&W2[(k + 0) * OUT_D + c]);
        float w1 = __ldg(&W2[(k + 1) * OUT_D + c]);
        float w2 = __ldg(&W2[(k + 2) * OUT_D + c]);
        float w3 = __ldg(&W2[(k + 3) * OUT_D + c]);
        unsigned long long wA = pack2(w0, w1);
        unsigned long long wB = pack2(w2, w3);
#pragma unroll
        for (int q = 0; q < 4; q++) {
            ulonglong2 x = *(const ulonglong2*)&xs[jg * 4 + q][k];
            ffma2(acc2[q], wA, x.x);
            ffma2(acc2[q], wB, x.y);
        }
    }
    float av = al[c], rv = ar[c];
#pragma unroll
    for (int q = 0; q < 4; q++) {
        int row = n0 + jg * 4 + q;
        float z = hsum2(acc2[q]);
        if (row < n) g_z2h[(size_t)row * OUT_D + c] = __float2half_rn(z);
        float el = z * av, er = z * rv;
#pragma unroll
        for (int off = 16; off; off >>= 1) {
            el += __shfl_xor_sync(0xffffffffu, el, off);
            er += __shfl_xor_sync(0xffffffffu, er, off);
        }
        if (lane == 0 && row < n) { g_el2[row] = el; g_er2[row] = er; }
    }
}

// aggregation layer2: one warp per node; 4 edges in flight (quarter-warps)
__global__ void k_aggr2(float* __restrict__ out, const float* __restrict__ b2, int n) {
    int d = blockIdx.x * (blockDim.x >> 5) + (threadIdx.x >> 5);
    if (d >= n) return;
    int lane = threadIdx.x & 31;
    int quarter = lane >> 3;
    int q = lane & 7;
    float er = g_er2[d];
    int beg = g_rowstart[d];
    int end = beg + g_cnt[d];
    float acc[4] = {0.f, 0.f, 0.f, 0.f};
    float sacc = 0.f;
    int i = beg + quarter;
    for (; i + 4 < end; i += 8) {
        int s0 = __ldg(&g_csrsrc[i]);
        int s1 = __ldg(&g_csrsrc[i + 4]);
        float e0 = __ldg(&g_el2[s0]);
        float e1 = __ldg(&g_el2[s1]);
        uint2 u0 = *(const uint2*)&g_z2h[(size_t)s0 * OUT_D + q * 4];
        uint2 u1 = *(const uint2*)&g_z2h[(size_t)s1 * OUT_D + q * 4];
        float x0 = __expf(lrelu(e0 + er));
        float x1 = __expf(lrelu(e1 + er));
        sacc += x0 + x1;
        float2 a0 = __half22float2(*(__half2*)&u0.x);
        float2 b0 = __half22float2(*(__half2*)&u0.y);
        float2 a1 = __half22float2(*(__half2*)&u1.x);
        float2 b1v = __half22float2(*(__half2*)&u1.y);
        acc[0] += x0 * a0.x + x1 * a1.x;
        acc[1] += x0 * a0.y + x1 * a1.y;
        acc[2] += x0 * b0.x + x1 * b1v.x;
        acc[3] += x0 * b0.y + x1 * b1v.y;
    }
    for (; i < end; i += 4) {
        int s0 = __ldg(&g_csrsrc[i]);
        float e0 = __ldg(&g_el2[s0]);
        uint2 u0 = *(const uint2*)&g_z2h[(size_t)s0 * OUT_D + q * 4];
        float x0 = __expf(lrelu(e0 + er));
        sacc += x0;
        float2 a0 = __half22float2(*(__half2*)&u0.x);
        float2 b0 = __half22float2(*(__half2*)&u0.y);
        acc[0] += x0 * a0.x;
        acc[1] += x0 * a0.y;
        acc[2] += x0 * b0.x;
        acc[3] += x0 * b0.y;
    }
#pragma unroll
    for (int off = 8; off <= 16; off <<= 1) {
        sacc += __shfl_xor_sync(0xffffffffu, sacc, off);
#pragma unroll
        for (int k = 0; k < 4; k++)
            acc[k] += __shfl_xor_sync(0xffffffffu, acc[k], off);
    }
    if (lane < 8) {
        float inv = (sacc > 0.f) ? __fdividef(1.f, sacc) : 0.f;
        float4 bb = *(const float4*)&b2[q * 4];
        float4 o;
        o.x = acc[0] * inv + bb.x;
        o.y = acc[1] * inv + bb.y;
        o.z = acc[2] * inv + bb.z;
        o.w = acc[3] * inv + bb.w;
        *(float4*)&out[(size_t)d * OUT_D + q * 4] = o;
    }
}

extern "C" void kernel_launch(void* const* d_in, const int* in_sizes, int n_in,
                              void* d_out, int out_size) {
    const float* h   = (const float*)d_in[0];
    const int*   src = (const int*)d_in[1];
    const int*   dst = (const int*)d_in[2];
    const float* W1  = (const float*)d_in[3];
    const float* al1 = (const float*)d_in[4];
    const float* ar1 = (const float*)d_in[5];
    const float* b1  = (const float*)d_in[6];
    const float* W2  = (const float*)d_in[7];
    const float* al2 = (const float*)d_in[8];
    const float* ar2 = (const float*)d_in[9];
    const float* b2  = (const float*)d_in[10];
    float* out = (float*)d_out;

    int n = in_sizes[0] / IN_DIM;
    int E = in_sizes[1];
    if (n > NMAX) n = NMAX;
    if (E > EMAX) E = EMAX;

    static cudaStream_t s2 = nullptr, s3 = nullptr;
    static cudaEvent_t evF = nullptr, evCSR = nullptr, evG1 = nullptr;
    static void* p_cnt = nullptr;
    static void* p_total = nullptr;
    if (s2 == nullptr) {
        cudaStreamCreateWithFlags(&s2, cudaStreamNonBlocking);
        cudaStreamCreateWithFlags(&s3, cudaStreamNonBlocking);
        cudaEventCreateWithFlags(&evF, cudaEventDisableTiming);
        cudaEventCreateWithFlags(&evCSR, cudaEventDisableTiming);
        cudaEventCreateWithFlags(&evG1, cudaEventDisableTiming);
        cudaGetSymbolAddress(&p_cnt, g_cnt);
        cudaGetSymbolAddress(&p_total, g_total);
    }

    // fork: both branches on non-legacy streams
    cudaEventRecord(evF, 0);
    cudaStreamWaitEvent(s2, evF, 0);
    cudaStreamWaitEvent(s3, evF, 0);

    // branch A (s2): CSR build
    cudaMemsetAsync(p_cnt, 0, (size_t)n * sizeof(int), s2);
    cudaMemsetAsync(p_total, 0, sizeof(int), s2);
    k_hist<<<(E / 16 + 255) / 256, 256, 0, s2>>>(dst, E);
    k_offsets<<<(n + 255) / 256, 256, 0, s2>>>(n);
    k_scatter<<<(E / 16 + 255) / 256, 256, 0, s2>>>(src, dst, E);
    cudaEventRecord(evCSR, s2);

    // branch B (s3): W1->fp16 then tensor-core GEMM1
    k_w1h<<<(IN_DIM * F1 + 255) / 256, 256, 0, s3>>>(W1);
    k_gemm1<<<(n + 31) / 32, 128, 0, s3>>>(h, al1, ar1, n);
    cudaEventRecord(evG1, s3);

    // join
    cudaStreamWaitEvent(0, evCSR, 0);
    cudaStreamWaitEvent(0, evG1, 0);

    k_aggr1<<<(n + 7) / 8, 256>>>(b1, n);
    k_gemm2<<<(n + 15) / 16, 128>>>(W2, al2, ar2, n);
    k_aggr2<<<(n + 7) / 8, 256>>>(out, b2, n);
}

// round 16
// speedup vs baseline: 1.0443x; 1.0431x over previous
#include <cuda_runtime.h>
#include <cuda_fp16.h>
#include <mma.h>
#include <math.h>

using namespace nvcuda;

#define NMAX 50000
#define EMAX 1600000
#define IN_DIM 128
#define F1 128          // HEADS*HID
#define HEADS 4
#define OUT_D 32

// ---- scratch (static __device__, no allocation) ----
__device__ __half g_W1h[IN_DIM * F1];        // fp16 copy of W1
__device__ __half g_z1h[NMAX * F1];          // fp16 layer1 linear output (gather payload)
__device__ float g_el1[NMAX * HEADS];
__device__ float g_er1[NMAX * HEADS];
__device__ float g_x1[NMAX * F1];            // layer1 output (normalized + bias + elu)
__device__ __half g_z2h[NMAX * OUT_D];       // fp16 layer2 linear output
__device__ float g_el2[NMAX];
__device__ float g_er2[NMAX];
// CSR
__device__ int g_cnt[NMAX];
__device__ int g_rowstart[NMAX];
__device__ int g_rank[EMAX];
__device__ int g_csrsrc[EMAX];
__device__ int g_total;

__device__ __forceinline__ float lrelu(float v) { return v > 0.f ? v : 0.2f * v; }
__device__ __forceinline__ float elu1(float v) { return v > 0.f ? v : expm1f(v); }

// ---- packed fp32x2 FMA ----
__device__ __forceinline__ unsigned long long pack2(float a, float b) {
    unsigned long long r;
    asm("mov.b64 %0, {%1, %2};" : "=l"(r) : "f"(a), "f"(b));
    return r;
}
__device__ __forceinline__ void ffma2(unsigned long long& acc, unsigned long long a,
                                      unsigned long long b) {
    asm("fma.rn.f32x2 %0, %1, %2, %0;" : "+l"(acc) : "l"(a), "l"(b));
}
__device__ __forceinline__ float hsum2(unsigned long long v) {
    float lo, hi;
    asm("mov.b64 {%0, %1}, %2;" : "=f"(lo), "=f"(hi) : "l"(v));
    return lo + hi;
}

// ================= CSR build (8 edges/thread) =================
__global__ void k_hist(const int* __restrict__ dst, int E) {
    int e = (blockIdx.x * blockDim.x + threadIdx.x) * 8;
    if (e + 7 < E) {
        int4 dA = *(const int4*)&dst[e];
        int4 dB = *(const int4*)&dst[e + 4];
        int4 rA, rB;
        rA.x = atomicAdd(&g_cnt[dA.x], 1);
        rA.y = atomicAdd(&g_cnt[dA.y], 1);
        rA.z = atomicAdd(&g_cnt[dA.z], 1);
        rA.w = atomicAdd(&g_cnt[dA.w], 1);
        rB.x = atomicAdd(&g_cnt[dB.x], 1);
        rB.y = atomicAdd(&g_cnt[dB.y], 1);
        rB.z = atomicAdd(&g_cnt[dB.z], 1);
        rB.w = atomicAdd(&g_cnt[dB.w], 1);
        *(int4*)&g_rank[e] = rA;
        *(int4*)&g_rank[e + 4] = rB;
    } else {
        for (int r = 0; r < 8; r++)
            if (e + r < E) g_rank[e + r] = atomicAdd(&g_cnt[dst[e + r]], 1);
    }
}

__global__ void k_offsets(int n) {
    int i = blockIdx.x * blockDim.x + threadIdx.x;
    int lane = threadIdx.x & 31;
    int c = (i < n) ? g_cnt[i] : 0;
    int inc = c;
#pragma unroll
    for (int off = 1; off < 32; off <<= 1) {
        int v = __shfl_up_sync(0xffffffffu, inc, off);
        if (lane >= off) inc += v;
    }
    int total = __shfl_sync(0xffffffffu, inc, 31);
    int base = 0;
    if (lane == 31) base = atomicAdd(&g_total, total);
    base = __shfl_sync(0xffffffffu, base, 31);
    if (i < n) g_rowstart[i] = base + inc - c;
}

__global__ void k_scatter(const int* __restrict__ src, const int* __restrict__ dst, int E) {
    int e = (blockIdx.x * blockDim.x + threadIdx.x) * 8;
    if (e + 7 < E) {
        int4 dA = *(const int4*)&dst[e];
        int4 dB = *(const int4*)&dst[e + 4];
        int4 sA = *(const int4*)&src[e];
        int4 sB = *(const int4*)&src[e + 4];
        int4 rA = *(const int4*)&g_rank[e];
        int4 rB = *(const int4*)&g_rank[e + 4];
        g_csrsrc[g_rowstart[dA.x] + rA.x] = sA.x;
        g_csrsrc[g_rowstart[dA.y] + rA.y] = sA.y;
        g_csrsrc[g_rowstart[dA.z] + rA.z] = sA.z;
        g_csrsrc[g_rowstart[dA.w] + rA.w] = sA.w;
        g_csrsrc[g_rowstart[dB.x] + rB.x] = sB.x;
        g_csrsrc[g_rowstart[dB.y] + rB.y] = sB.y;
        g_csrsrc[g_rowstart[dB.z] + rB.z] = sB.z;
        g_csrsrc[g_rowstart[dB.w] + rB.w] = sB.w;
    } else {
        for (int r = 0; r < 8; r++) {
            if (e + r < E)
                g_csrsrc[g_rowstart[dst[e + r]] + g_rank[e + r]] = src[e + r];
        }
    }
}

// ================= layer 1 =================
__global__ void k_w1h(const float* __restrict__ W1) {
    int i = blockIdx.x * blockDim.x + threadIdx.x;
    if (i < IN_DIM * F1) g_W1h[i] = __float2half_rn(W1[i]);
}

// GEMM1 via wmma (HMMA): 32 rows/block, 128 threads (4 warps).
__global__ void __launch_bounds__(128) k_gemm1(
    const float* __restrict__ h, const float* __restrict__ al,
    const float* __restrict__ ar, int n) {
    __shared__ __align__(16) __half As[32][136];
    __shared__ __align__(16) float Cs[32][128];
    int n0 = blockIdx.x * 32;
    int t = threadIdx.x;

    for (int idx = t; idx < 32 * IN_DIM; idx += 128) {
        int r = idx >> 7, c = idx & 127;
        int gr = n0 + r;
        float v = (gr < n) ? h[(size_t)gr * IN_DIM + c] : 0.f;
        As[r][c] = __float2half_rn(v);
    }
    __syncthreads();

    int w = t >> 5;
    int mt = w & 1;
    int c0 = (w >> 1) * 4;

    wmma::fragment<wmma::accumulator, 16, 16, 16, float> acc[4];
#pragma unroll
    for (int q = 0; q < 4; q++) wmma::fill_fragment(acc[q], 0.f);

#pragma unroll
    for (int k = 0; k < 8; k++) {
        wmma::fragment<wmma::matrix_a, 16, 16, 16, __half, wmma::row_major> a;
        wmma::load_matrix_sync(a, &As[mt * 16][k * 16], 136);
#pragma unroll
        for (int q = 0; q < 4; q++) {
            wmma::fragment<wmma::matrix_b, 16, 16, 16, __half, wmma::row_major> b;
            wmma::load_matrix_sync(b, &g_W1h[(k * 16) * F1 + (c0 + q) * 16], F1);
            wmma::mma_sync(acc[q], a, b, acc[q]);
        }
    }
#pragma unroll
    for (int q = 0; q < 4; q++)
        wmma::store_matrix_sync(&Cs[mt * 16][(c0 + q) * 16], acc[q], 128,
                                wmma::mem_row_major);
    __syncthreads();

    int lane = t & 31;
    int hh = t >> 5;
    float av = al[t], rv = ar[t];
    for (int r = 0; r < 32; r++) {
        int row = n0 + r;
        float z = Cs[r][t];
        if (row < n) g_z1h[(size_t)row * F1 + t] = __float2half_rn(z);
        float el = z * av, er = z * rv;
#pragma unroll
        for (int off = 16; off; off >>= 1) {
            el += __shfl_xor_sync(0xffffffffu, el, off);
            er += __shfl_xor_sync(0xffffffffu, er, off);
        }
        if (lane == 0 && row < n) {
            g_el1[row * HEADS + hh] = el;
            g_er1[row * HEADS + hh] = er;
        }
    }
}

// aggregation layer1: one warp per node; 2 edges in flight (half-warps).
// Main loop runs a WARP-UNIFORM number of 8-edge iterations (nfull = cnt/8)
// so the exp-dedup shuffles are always full-warp; tail uses no shuffles.
__global__ void k_aggr1(const float* __restrict__ b1, int n) {
    int d = blockIdx.x * (blockDim.x >> 5) + (threadIdx.x >> 5);
    if (d >= n) return;
    int lane = threadIdx.x & 31;
    int half = lane >> 4;
    int l = lane & 15;            // channel group: channels 8l..8l+7
    int hh = l >> 2;              // head of this channel group
    int u0 = l & 3;               // the edge this lane computes exp for
    float er = g_er1[d * HEADS + hh];
    int beg = g_rowstart[d];
    int cnt = g_cnt[d];
    int end = beg + cnt;
    int nfull = cnt >> 3;         // warp-uniform full 8-edge iterations
    float acc[8] = {0.f, 0.f, 0.f, 0.f, 0.f, 0.f, 0.f, 0.f};
    float sacc = 0.f;
    int i = beg + half;
    for (int it = 0; it < nfull; it++, i += 8) {
        int s[4];
#pragma unroll
        for (int u = 0; u < 4; u++) s[u] = __ldg(&g_csrsrc[i + 2 * u]);
        // one el load + one exp per lane (covers 4 edges x 4 heads per half)
        float e_own = __ldg(&g_el1[s[u0] * HEADS + hh]);
        uint4 uz[4];
#pragma unroll
        for (int u = 0; u < 4; u++)
            uz[u] = *(const uint4*)&g_z1h[(size_t)s[u] * F1 + l * 8];
        float x_own = __expf(lrelu(e_own + er));
        float xs[4];
#pragma unroll
        for (int u = 0; u < 4; u++)
            xs[u] = __shfl_sync(0xffffffffu, x_own, (lane & ~3) | u);
        sacc += (xs[0] + xs[1]) + (xs[2] + xs[3]);
#pragma unroll
        for (int u = 0; u < 4; u++) {
            float x = xs[u];
            float2 p0 = __half22float2(*(__half2*)&uz[u].x);
            float2 p1 = __half22float2(*(__half2*)&uz[u].y);
            float2 p2 = __half22float2(*(__half2*)&uz[u].z);
            float2 p3 = __half22float2(*(__half2*)&uz[u].w);
            acc[0] += x * p0.x; acc[1] += x * p0.y;
            acc[2] += x * p1.x; acc[3] += x * p1.y;
            acc[4] += x * p2.x; acc[5] += x * p2.y;
            acc[6] += x * p3.x; acc[7] += x * p3.y;
        }
    }
    // tail (< 8 edges): no shuffles, per-lane redundant exp (R12 style)
    for (; i < end; i += 2) {
        int s0 = __ldg(&g_csrsrc[i]);
        float e0 = __ldg(&g_el1[s0 * HEADS + hh]);
        uint4 uz = *(const uint4*)&g_z1h[(size_t)s0 * F1 + l * 8];
        float x = __expf(lrelu(e0 + er));
        sacc += x;
        float2 p0 = __half22float2(*(__half2*)&uz.x);
        float2 p1 = __half22float2(*(__half2*)&uz.y);
        float2 p2 = __half22float2(*(__half2*)&uz.z);
        float2 p3 = __half22float2(*(__half2*)&uz.w);
        acc[0] += x * p0.x; acc[1] += x * p0.y;
        acc[2] += x * p1.x; acc[3] += x * p1.y;
        acc[4] += x * p2.x; acc[5] += x * p2.y;
        acc[6] += x * p3.x; acc[7] += x * p3.y;
    }
    // merge halves
    sacc += __shfl_xor_sync(0xffffffffu, sacc, 16);
#pragma unroll
    for (int k = 0; k < 8; k++)
        acc[k] += __shfl_xor_sync(0xffffffffu, acc[k], 16);
    if (half == 0) {
        float inv = (sacc > 0.f) ? __fdividef(1.f, sacc) : 0.f;
        float4 bA = *(const float4*)&b1[l * 8];
        float4 bB = *(const float4*)&b1[l * 8 + 4];
        float4 o1, o2;
        o1.x = elu1(acc[0] * inv + bA.x);
        o1.y = elu1(acc[1] * inv + bA.y);
        o1.z = elu1(acc[2] * inv + bA.z);
        o1.w = elu1(acc[3] * inv + bA.w);
        o2.x = elu1(acc[4] * inv + bB.x);
        o2.y = elu1(acc[5] * inv + bB.y);
        o2.z = elu1(acc[6] * inv + bB.z);
        o2.w = elu1(acc[7] * inv + bB.w);
        *(float4*)&g_x1[(size_t)d * F1 + l * 8] = o1;
        *(float4*)&g_x1[(size_t)d * F1 + l * 8 + 4] = o2;
    }
}

// ================= layer 2 =================
__global__ void k_gemm2(const float* __restrict__ W2, const float* __restrict__ al,
                        const float* __restrict__ ar, int n) {
    __shared__ float xs[16][IN_DIM];
    int n0 = blockIdx.x * 16;
    int t = threadIdx.x;
    int lane = t & 31;
#pragma unroll
    for (int j = 0; j < 16; j++) {
        int row = n0 + j;
        xs[j][t] = (row < n) ? g_x1[(size_t)row * F1 + t] : 0.f;
    }
    __syncthreads();
    int c = t & 31;
    int jg = t >> 5;
    unsigned long long acc2[4] = {0ull, 0ull, 0ull, 0ull};
#pragma unroll 2
    for (int k = 0; k < IN_DIM; k += 4) {
        float w0 = __ldg(&W2[(k + 0) * OUT_D + c]);
        float w1 = __ldg(&W2[(k + 1) * OUT_D + c]);
        float w2 = __ldg(&W2[(k + 2) * OUT_D + c]);
        float w3 = __ldg(&W2[(k + 3) * OUT_D + c]);
        unsigned long long wA = pack2(w0, w1);
        unsigned long long wB = pack2(w2, w3);
#pragma unroll
        for (int q = 0; q < 4; q++) {
            ulonglong2 x = *(const ulonglong2*)&xs[jg * 4 + q][k];
            ffma2(acc2[q], wA, x.x);
            ffma2(acc2[q], wB, x.y);
        }
    }
    float av = al[c], rv = ar[c];
#pragma unroll
    for (int q = 0; q < 4; q++) {
        int row = n0 + jg * 4 + q;
        float z = hsum2(acc2[q]);
        if (row < n) g_z2h[(size_t)row * OUT_D + c] = __float2half_rn(z);
        float el = z * av, er = z * rv;
#pragma unroll
        for (int off = 16; off; off >>= 1) {
            el += __shfl_xor_sync(0xffffffffu, el, off);
            er += __shfl_xor_sync(0xffffffffu, er, off);
        }
        if (lane == 0 && row < n) { g_el2[row] = el; g_er2[row] = er; }
    }
}

// aggregation layer2: one warp per node; 4 edges in flight (quarter-warps).
// Warp-uniform main loop (nfull = cnt/8) for safe exp-dedup shuffles.
__global__ void k_aggr2(float* __restrict__ out, const float* __restrict__ b2, int n) {
    int d = blockIdx.x * (blockDim.x >> 5) + (threadIdx.x >> 5);
    if (d >= n) return;
    int lane = threadIdx.x & 31;
    int quarter = lane >> 3;
    int q = lane & 7;
    int u0 = q & 1;
    float er = g_er2[d];
    int beg = g_rowstart[d];
    int cnt = g_cnt[d];
    int end = beg + cnt;
    int nfull = cnt >> 3;         // warp-uniform 8-edge iterations
    float acc[4] = {0.f, 0.f, 0.f, 0.f};
    float sacc = 0.f;
    int i = beg + quarter;
    for (int it = 0; it < nfull; it++, i += 8) {
        int s0 = __ldg(&g_csrsrc[i]);
        int s1 = __ldg(&g_csrsrc[i + 4]);
        float e_own = __ldg(&g_el2[u0 ? s1 : s0]);
        uint2 z0 = *(const uint2*)&g_z2h[(size_t)s0 * OUT_D + q * 4];
        uint2 z1 = *(const uint2*)&g_z2h[(size_t)s1 * OUT_D + q * 4];
        float x_own = __expf(lrelu(e_own + er));
        float x0 = __shfl_sync(0xffffffffu, x_own, lane & ~1);
        float x1 = __shfl_sync(0xffffffffu, x_own, (lane & ~1) | 1);
        sacc += x0 + x1;
        float2 a0 = __half22float2(*(__half2*)&z0.x);
        float2 b0 = __half22float2(*(__half2*)&z0.y);
        float2 a1 = __half22float2(*(__half2*)&z1.x);
        float2 b1v = __half22float2(*(__half2*)&z1.y);
        acc[0] += x0 * a0.x + x1 * a1.x;
        acc[1] += x0 * a0.y + x1 * a1.y;
        acc[2] += x0 * b0.x + x1 * b1v.x;
        acc[3] += x0 * b0.y + x1 * b1v.y;
    }
    // tail: no shuffles, per-lane redundant exp
    for (; i < end; i += 4) {
        int s0 = __ldg(&g_csrsrc[i]);
        float e0 = __ldg(&g_el2[s0]);
        uint2 z0 = *(const uint2*)&g_z2h[(size_t)s0 * OUT_D + q * 4];
        float x0 = __expf(lrelu(e0 + er));
        sacc += x0;
        float2 a0 = __half22float2(*(__half2*)&z0.x);
        float2 b0 = __half22float2(*(__half2*)&z0.y);
        acc[0] += x0 * a0.x;
        acc[1] += x0 * a0.y;
        acc[2] += x0 * b0.x;
        acc[3] += x0 * b0.y;
    }
#pragma unroll
    for (int off = 8; off <= 16; off <<= 1) {
        sacc += __shfl_xor_sync(0xffffffffu, sacc, off);
#pragma unroll
        for (int k = 0; k < 4; k++)
            acc[k] += __shfl_xor_sync(0xffffffffu, acc[k], off);
    }
    if (lane < 8) {
        float inv = (sacc > 0.f) ? __fdividef(1.f, sacc) : 0.f;
        float4 bb = *(const float4*)&b2[q * 4];
        float4 o;
        o.x = acc[0] * inv + bb.x;
        o.y = acc[1] * inv + bb.y;
        o.z = acc[2] * inv + bb.z;
        o.w = acc[3] * inv + bb.w;
        *(float4*)&out[(size_t)d * OUT_D + q * 4] = o;
    }
}

extern "C" void kernel_launch(void* const* d_in, const int* in_sizes, int n_in,
                              void* d_out, int out_size) {
    const float* h   = (const float*)d_in[0];
    const int*   src = (const int*)d_in[1];
    const int*   dst = (const int*)d_in[2];
    const float* W1  = (const float*)d_in[3];
    const float* al1 = (const float*)d_in[4];
    const float* ar1 = (const float*)d_in[5];
    const float* b1  = (const float*)d_in[6];
    const float* W2  = (const float*)d_in[7];
    const float* al2 = (const float*)d_in[8];
    const float* ar2 = (const float*)d_in[9];
    const float* b2  = (const float*)d_in[10];
    float* out = (float*)d_out;

    int n = in_sizes[0] / IN_DIM;
    int E = in_sizes[1];
    if (n > NMAX) n = NMAX;
    if (E > EMAX) E = EMAX;

    static cudaStream_t s2 = nullptr, s3 = nullptr;
    static cudaEvent_t evF = nullptr, evCSR = nullptr, evG1 = nullptr;
    static void* p_cnt = nullptr;
    static void* p_total = nullptr;
    if (s2 == nullptr) {
        cudaStreamCreateWithFlags(&s2, cudaStreamNonBlocking);
        cudaStreamCreateWithFlags(&s3, cudaStreamNonBlocking);
        cudaEventCreateWithFlags(&evF, cudaEventDisableTiming);
        cudaEventCreateWithFlags(&evCSR, cudaEventDisableTiming);
        cudaEventCreateWithFlags(&evG1, cudaEventDisableTiming);
        cudaGetSymbolAddress(&p_cnt, g_cnt);
        cudaGetSymbolAddress(&p_total, g_total);
    }

    // fork: both branches on non-legacy streams
    cudaEventRecord(evF, 0);
    cudaStreamWaitEvent(s2, evF, 0);
    cudaStreamWaitEvent(s3, evF, 0);

    // branch A (s2): CSR build
    cudaMemsetAsync(p_cnt, 0, (size_t)n * sizeof(int), s2);
    cudaMemsetAsync(p_total, 0, sizeof(int), s2);
    k_hist<<<(E / 8 + 255) / 256, 256, 0, s2>>>(dst, E);
    k_offsets<<<(n + 255) / 256, 256, 0, s2>>>(n);
    k_scatter<<<(E / 8 + 255) / 256, 256, 0, s2>>>(src, dst, E);
    cudaEventRecord(evCSR, s2);

    // branch B (s3): W1->fp16 then tensor-core GEMM1
    k_w1h<<<(IN_DIM * F1 + 255) / 256, 256, 0, s3>>>(W1);
    k_gemm1<<<(n + 31) / 32, 128, 0, s3>>>(h, al1, ar1, n);
    cudaEventRecord(evG1, s3);

    // join
    cudaStreamWaitEvent(0, evCSR, 0);
    cudaStreamWaitEvent(0, evG1, 0);

    k_aggr1<<<(n + 7) / 8, 256>>>(b1, n);
    k_gemm2<<<(n + 15) / 16, 128>>>(W2, al2, ar2, n);
    k_aggr2<<<(n + 7) / 8, 256>>>(out, b2, n);
}